// round 1
// baseline (speedup 1.0000x reference)
#include <cuda_runtime.h>
#include <cstdint>

// ---------------- problem constants ----------------
#define NX 64
#define NY 64
#define NZc 32
#define NNXc 65
#define NNYc 65
#define NNZc 33
#define NNODES (NNXc*NNYc*NNZc)      // 139425
#define NCELLS (NX*NY*NZc)           // 131072
#define NACT   (NX*NY*20)            // 81920
#define NSRC   16
#define EPSD   1.0e-7f
#define ATOL2  2.0e-12               // (1e-6)^2 * ||b||^2, ||b||^2 = 2
#define NCX (64*65*33)               // 137280
#define NCY (65*64*33)               // 137280
#define NCZ (65*65*32)               // 135200
#define CG_ITERS 100

// ---------------- device scratch (static, no allocation) ----------------
__device__ float4 g_x [NNODES*4];
__device__ float4 g_r [NNODES*4];
__device__ float4 g_pA[NNODES*4];
__device__ float4 g_pB[NNODES*4];
__device__ float4 g_q [NNODES*4];
__device__ float  g_sigma[NCELLS];
__device__ float  g_cx[NCX];
__device__ float  g_cy[NCY];
__device__ float  g_cz[NCZ];
__device__ double g_pq[16];
__device__ double g_g2[16];
__device__ float4 g_alpha[4];
__device__ float4 g_beta[4];
__device__ float  g_gamma[16];
__device__ int    g_frozen[16];

// ---------------- float4 helpers ----------------
__device__ __forceinline__ float4 f4add(float4 a, float4 b){ return make_float4(a.x+b.x,a.y+b.y,a.z+b.z,a.w+b.w); }
__device__ __forceinline__ float4 f4sub(float4 a, float4 b){ return make_float4(a.x-b.x,a.y-b.y,a.z-b.z,a.w-b.w); }
__device__ __forceinline__ float4 f4mul(float4 a, float4 b){ return make_float4(a.x*b.x,a.y*b.y,a.z*b.z,a.w*b.w); }
__device__ __forceinline__ float4 f4scale(float4 a, float s){ return make_float4(a.x*s,a.y*s,a.z*s,a.w*s); }
__device__ __forceinline__ float4 f4fma(float4 a, float4 b, float4 c){
    return make_float4(fmaf(a.x,b.x,c.x), fmaf(a.y,b.y,c.y), fmaf(a.z,b.z,c.z), fmaf(a.w,b.w,c.w));
}

// ---------------- init kernels ----------------
__global__ void k_init_sigma() {
    int t = blockIdx.x*blockDim.x + threadIdx.x;
    if (t < NCELLS) g_sigma[t] = 1.0e-8f;       // 1/AIR_RES
}

__global__ void k_scatter(const int* __restrict__ act, const float* __restrict__ model) {
    int t = blockIdx.x*blockDim.x + threadIdx.x;
    if (t < NACT) g_sigma[act[t]] = 1.0f / model[t];
}

__global__ void k_coeffs() {
    int t = blockIdx.x*blockDim.x + threadIdx.x;
    if (t < NCX) {
        int k = t % 33; int r = t / 33; int j = r % 65; int i = r / 65;
        float s = 0.f;
        #pragma unroll
        for (int jj = j-1; jj <= j; ++jj)
            #pragma unroll
            for (int kk = k-1; kk <= k; ++kk)
                if (jj >= 0 && jj < NY && kk >= 0 && kk < NZc)
                    s += g_sigma[(i*NY + jj)*NZc + kk];
        g_cx[t] = 6.25f * s;                     // 0.25 * 25.0
    } else if (t < NCX + NCY) {
        int e = t - NCX;
        int k = e % 33; int r = e / 33; int j = r % 64; int i = r / 64;
        float s = 0.f;
        #pragma unroll
        for (int ii = i-1; ii <= i; ++ii)
            #pragma unroll
            for (int kk = k-1; kk <= k; ++kk)
                if (ii >= 0 && ii < NX && kk >= 0 && kk < NZc)
                    s += g_sigma[(ii*NY + j)*NZc + kk];
        g_cy[e] = 6.25f * s;
    } else if (t < NCX + NCY + NCZ) {
        int e = t - NCX - NCY;
        int k = e % 32; int r = e / 32; int j = r % 65; int i = r / 65;
        float s = 0.f;
        #pragma unroll
        for (int ii = i-1; ii <= i; ++ii)
            #pragma unroll
            for (int jj = j-1; jj <= j; ++jj)
                if (ii >= 0 && ii < NX && jj >= 0 && jj < NY)
                    s += g_sigma[(ii*NY + jj)*NZc + k];
        g_cz[e] = 6.25f * s;
    }
}

__global__ void k_initvec() {
    int t = blockIdx.x*blockDim.x + threadIdx.x;
    if (t < NNODES*4) {
        float4 z = make_float4(0.f,0.f,0.f,0.f);
        g_x[t] = z; g_r[t] = z; g_pA[t] = z;
    }
}

__global__ void k_setb(const int* __restrict__ sa, const int* __restrict__ sb) {
    int s = threadIdx.x;
    if (s < NSRC) {
        float* rf = (float*)g_r;
        rf[sa[s]*16 + s]  = 1.0f;
        rf[sb[s]*16 + s] -= 1.0f;                // sa != sb here
        g_gamma[s]  = 2.0f;                      // ||b||^2
        g_frozen[s] = 0;
        g_pq[s]     = 0.0;
        ((float*)g_beta)[s] = 0.f;
    }
}

// ---------------- CG iteration kernels ----------------
// K_A: p_new = r + beta*p_old (double buffered); q = A p_new; reduce p.q
__global__ void __launch_bounds__(256) k_apA(int par) {
    int t = blockIdx.x*256 + threadIdx.x;
    int node = t >> 2, q4 = t & 3;
    float4 partial = make_float4(0.f,0.f,0.f,0.f);
    if (node < NNODES) {
        const float4* __restrict__ pin  = par ? g_pB : g_pA;
        float4* __restrict__       pout = par ? g_pA : g_pB;
        int k  = node % NNZc;
        int ij = node / NNZc;
        int j  = ij % NNYc;
        int i  = ij / NNYc;
        float4 beta = g_beta[q4];
        int base = node*4 + q4;

        float4 pc  = f4fma(beta, pin[base], g_r[base]);
        float4 acc = f4scale(pc, EPSD);

        if (i < NNXc-1) {
            float  c  = g_cx[(i*65 + j)*33 + k];
            float4 pn = f4fma(beta, pin[base + 4*2145], g_r[base + 4*2145]);
            acc = f4add(acc, f4scale(f4sub(pc, pn), c));
        }
        if (i > 0) {
            float  c  = g_cx[((i-1)*65 + j)*33 + k];
            float4 pn = f4fma(beta, pin[base - 4*2145], g_r[base - 4*2145]);
            acc = f4add(acc, f4scale(f4sub(pc, pn), c));
        }
        if (j < NNYc-1) {
            float  c  = g_cy[(i*64 + j)*33 + k];
            float4 pn = f4fma(beta, pin[base + 4*33], g_r[base + 4*33]);
            acc = f4add(acc, f4scale(f4sub(pc, pn), c));
        }
        if (j > 0) {
            float  c  = g_cy[(i*64 + (j-1))*33 + k];
            float4 pn = f4fma(beta, pin[base - 4*33], g_r[base - 4*33]);
            acc = f4add(acc, f4scale(f4sub(pc, pn), c));
        }
        if (k < NNZc-1) {
            float  c  = g_cz[(i*65 + j)*32 + k];
            float4 pn = f4fma(beta, pin[base + 4], g_r[base + 4]);
            acc = f4add(acc, f4scale(f4sub(pc, pn), c));
        }
        if (k > 0) {
            float  c  = g_cz[(i*65 + j)*32 + (k-1)];
            float4 pn = f4fma(beta, pin[base - 4], g_r[base - 4]);
            acc = f4add(acc, f4scale(f4sub(pc, pn), c));
        }
        pout[base] = pc;
        g_q[base]  = acc;
        partial = f4mul(pc, acc);
    }
    __shared__ float4 red[256];
    red[threadIdx.x] = partial;
    __syncthreads();
    for (int off = 32; off >= 1; off >>= 1) {
        if ((threadIdx.x >> 2) < off)
            red[threadIdx.x] = f4add(red[threadIdx.x], red[threadIdx.x + off*4]);
        __syncthreads();
    }
    if (threadIdx.x < 4) {
        float4 v = red[threadIdx.x];
        int s0 = threadIdx.x * 4;
        atomicAdd(&g_pq[s0+0], (double)v.x);
        atomicAdd(&g_pq[s0+1], (double)v.y);
        atomicAdd(&g_pq[s0+2], (double)v.z);
        atomicAdd(&g_pq[s0+3], (double)v.w);
    }
}

__global__ void k_alpha() {
    int s = threadIdx.x;
    if (s < NSRC) {
        float a = 0.f;
        if (!g_frozen[s]) a = g_gamma[s] / (float)g_pq[s];
        ((float*)g_alpha)[s] = a;
        g_g2[s] = 0.0;
    }
}

// K_C: x += alpha*p ; r -= alpha*q ; reduce r.r
__global__ void __launch_bounds__(256) k_xr(int par) {
    int t = blockIdx.x*256 + threadIdx.x;
    int node = t >> 2, q4 = t & 3;
    float4 partial = make_float4(0.f,0.f,0.f,0.f);
    if (node < NNODES) {
        const float4* __restrict__ pnew = par ? g_pA : g_pB;   // buffer K_A just wrote
        int base = node*4 + q4;
        float4 alpha = g_alpha[q4];
        float4 p  = pnew[base];
        float4 qv = g_q[base];
        g_x[base] = f4fma(alpha, p, g_x[base]);
        float4 rn = f4sub(g_r[base], f4mul(alpha, qv));
        g_r[base] = rn;
        partial = f4mul(rn, rn);
    }
    __shared__ float4 red[256];
    red[threadIdx.x] = partial;
    __syncthreads();
    for (int off = 32; off >= 1; off >>= 1) {
        if ((threadIdx.x >> 2) < off)
            red[threadIdx.x] = f4add(red[threadIdx.x], red[threadIdx.x + off*4]);
        __syncthreads();
    }
    if (threadIdx.x < 4) {
        float4 v = red[threadIdx.x];
        int s0 = threadIdx.x * 4;
        atomicAdd(&g_g2[s0+0], (double)v.x);
        atomicAdd(&g_g2[s0+1], (double)v.y);
        atomicAdd(&g_g2[s0+2], (double)v.z);
        atomicAdd(&g_g2[s0+3], (double)v.w);
    }
}

__global__ void k_beta() {
    int s = threadIdx.x;
    if (s < NSRC) {
        double gn = g_g2[s];
        float gamman = (float)gn;
        float b = 0.f;
        if (!g_frozen[s]) b = gamman / g_gamma[s];
        g_gamma[s] = gamman;
        if (gn <= ATOL2) g_frozen[s] = 1;        // jax cond: gamma > atol2
        ((float*)g_beta)[s] = b;
        g_pq[s] = 0.0;
    }
}

// ---------------- loss ----------------
__global__ void k_loss(const float* __restrict__ infm, const float* __restrict__ start,
                       const float* __restrict__ ref,  const int* __restrict__ rxm,
                       const int* __restrict__ rxn, float* __restrict__ out) {
    __shared__ double sd[256];
    __shared__ double sm[256];
    int t = threadIdx.x;
    const float* xf = (const float*)g_x;
    int s = t >> 4;                              // source index (flat = s*16 + r)
    int m = rxm[t], n = rxn[t];
    float d = xf[m*16 + s] - xf[n*16 + s];
    float diff = d - ref[t];
    sd[t] = (double)diff * (double)diff;
    double lm = 0.0;
    for (int idx = t; idx < NACT; idx += 256) {
        float dd = infm[idx] - start[idx];
        lm += (double)dd * (double)dd;
    }
    sm[t] = lm;
    __syncthreads();
    for (int off = 128; off >= 1; off >>= 1) {
        if (t < off) { sd[t] += sd[t+off]; sm[t] += sm[t+off]; }
        __syncthreads();
    }
    if (t == 0) {
        float loss_data  = (float)(sd[0] / 256.0);
        float loss_model = (float)(sm[0] / (double)NACT);
        out[0] = loss_data;     // alpha = 0.0 -> total == loss_data
        out[1] = loss_data;
        out[2] = loss_model;
    }
}

// ---------------- launch ----------------
extern "C" void kernel_launch(void* const* d_in, const int* in_sizes, int n_in,
                              void* d_out, int out_size) {
    const float* infm  = (const float*)d_in[0];
    const float* start = (const float*)d_in[1];
    const float* dref  = (const float*)d_in[2];
    const int*   act   = (const int*)  d_in[3];
    const int*   sa    = (const int*)  d_in[4];
    const int*   sb    = (const int*)  d_in[5];
    const int*   rxm   = (const int*)  d_in[6];
    const int*   rxn   = (const int*)  d_in[7];
    float* out = (float*)d_out;

    k_init_sigma<<<(NCELLS+255)/256, 256>>>();
    k_scatter<<<(NACT+255)/256, 256>>>(act, infm);
    k_coeffs<<<(NCX+NCY+NCZ+255)/256, 256>>>();
    k_initvec<<<(NNODES*4+255)/256, 256>>>();
    k_setb<<<1, 32>>>(sa, sb);

    const int grid = (NNODES*4 + 255)/256;       // 2179
    int par = 0;
    for (int it = 0; it < CG_ITERS; ++it) {
        k_apA<<<grid, 256>>>(par);
        k_alpha<<<1, 32>>>();
        k_xr<<<grid, 256>>>(par);
        k_beta<<<1, 32>>>();
        par ^= 1;
    }
    k_loss<<<1, 256>>>(infm, start, dref, rxm, rxn, out);
}

// round 2
// speedup vs baseline: 1.5271x; 1.5271x over previous
#include <cuda_runtime.h>

// ---------------- problem constants ----------------
#define NNODES 139425          // 65*65*33
#define NCELLS 131072          // 64*64*32
#define NACT   81920
#define EPSD   1.0e-7f
#define ATOL2  2.0e-12         // (1e-6)^2 * ||b||^2, ||b||^2 = 2
#define NCX 137280             // 64*65*33
#define NCY 137280             // 65*64*33
#define NCZ 135200             // 65*65*32
#define CG_ITERS 100
#define NBLK 148
#define NTHR 1024

// ---------------- device scratch ----------------
__device__ float4 g_p[NNODES*4];
__device__ float  g_sigma[NCELLS];
__device__ float  g_cx[NCX];
__device__ float  g_cy[NCY];
__device__ float  g_cz[NCZ];
__device__ float  g_pqpart[NBLK*16];
__device__ float  g_g2part[NBLK*16];
__device__ float  g_xsel[32*16];
__device__ volatile unsigned g_arr[NBLK];
__device__ volatile unsigned g_rel;

// ---------------- setup kernels ----------------
__global__ void k_init_sigma() {
    int t = blockIdx.x*blockDim.x + threadIdx.x;
    if (t < NCELLS) g_sigma[t] = 1.0e-8f;            // 1/AIR_RES
}

__global__ void k_scatter(const int* __restrict__ act, const float* __restrict__ model) {
    int t = blockIdx.x*blockDim.x + threadIdx.x;
    if (t < NACT) g_sigma[act[t]] = 1.0f / model[t];
}

__global__ void k_coeffs() {
    int t = blockIdx.x*blockDim.x + threadIdx.x;
    if (t < NCX) {
        int k = t % 33; int r = t / 33; int j = r % 65; int i = r / 65;
        float s = 0.f;
        for (int jj = j-1; jj <= j; ++jj)
            for (int kk = k-1; kk <= k; ++kk)
                if (jj >= 0 && jj < 64 && kk >= 0 && kk < 32)
                    s += g_sigma[(i*64 + jj)*32 + kk];
        g_cx[t] = 6.25f * s;                          // 0.25 * 25.0
    } else if (t < NCX + NCY) {
        int e = t - NCX;
        int k = e % 33; int r = e / 33; int j = r % 64; int i = r / 64;
        float s = 0.f;
        for (int ii = i-1; ii <= i; ++ii)
            for (int kk = k-1; kk <= k; ++kk)
                if (ii >= 0 && ii < 64 && kk >= 0 && kk < 32)
                    s += g_sigma[(ii*64 + j)*32 + kk];
        g_cy[e] = 6.25f * s;
    } else if (t < NCX + NCY + NCZ) {
        int e = t - NCX - NCY;
        int k = e % 32; int r = e / 32; int j = r % 65; int i = r / 65;
        float s = 0.f;
        for (int ii = i-1; ii <= i; ++ii)
            for (int jj = j-1; jj <= j; ++jj)
                if (ii >= 0 && ii < 64 && jj >= 0 && jj < 64)
                    s += g_sigma[(ii*64 + jj)*32 + k];
        g_cz[e] = 6.25f * s;
    }
}

// ---------------- software grid barrier ----------------
__device__ __forceinline__ void gsync(unsigned target) {
    __syncthreads();
    if (threadIdx.x == 0) {
        __threadfence();                 // flush + order this block's writes
        g_arr[blockIdx.x] = target;
    }
    if (blockIdx.x == 0) {
        if (threadIdx.x < 32) {
            for (int b = (int)threadIdx.x; b < NBLK; b += 32) {
                while (g_arr[b] < target) { }
            }
            __syncwarp();
            if (threadIdx.x == 0) { __threadfence(); g_rel = target; }
        }
    } else {
        if (threadIdx.x == 0) {
            while (g_rel < target) { }
            __threadfence();             // invalidate L1 -> see fresh data
        }
    }
    __syncthreads();
}

// block reduction: EXPR(s) summed over the block -> gout[0..15] (float)
#define BLOCKRED(EXPR, gout)                                                   \
    {                                                                          \
        _Pragma("unroll")                                                      \
        for (int s = 0; s < 16; s++) {                                         \
            float v = (EXPR);                                                  \
            v += __shfl_down_sync(0xffffffffu, v, 16);                         \
            v += __shfl_down_sync(0xffffffffu, v, 8);                          \
            v += __shfl_down_sync(0xffffffffu, v, 4);                          \
            v += __shfl_down_sync(0xffffffffu, v, 2);                          \
            v += __shfl_down_sync(0xffffffffu, v, 1);                          \
            if (lane == 0) s_red[wid*16 + s] = v;                              \
        }                                                                      \
        __syncthreads();                                                       \
        if (tid < 16) {                                                        \
            float acc = 0.f;                                                   \
            _Pragma("unroll")                                                  \
            for (int w = 0; w < 32; w++) acc += s_red[w*16 + tid];             \
            s_cross[tid] = acc;                                                \
        }                                                                      \
        __syncthreads();                                                       \
        if (tid == 0) {                                                        \
            float4* o = (float4*)(gout);                                       \
            const float4* c = (const float4*)s_cross;                          \
            o[0] = c[0]; o[1] = c[1]; o[2] = c[2]; o[3] = c[3];                \
        }                                                                      \
    }

// one stencil direction: q += c * (p - p_neighbor)
#define NB(nb4, cval)                                                          \
    {                                                                          \
        float c_ = (cval);                                                     \
        _Pragma("unroll")                                                      \
        for (int u = 0; u < 4; u++) {                                          \
            float4 pn = g_p[(nb4) + u];                                        \
            qq[4*u+0] += c_*(pp[4*u+0] - pn.x);                                \
            qq[4*u+1] += c_*(pp[4*u+1] - pn.y);                                \
            qq[4*u+2] += c_*(pp[4*u+2] - pn.z);                                \
            qq[4*u+3] += c_*(pp[4*u+3] - pn.w);                                \
        }                                                                      \
    }

// ---------------- persistent CG kernel ----------------
__global__ void __launch_bounds__(NTHR, 1)
k_persist(const int* __restrict__ sa, const int* __restrict__ sb,
          const int* __restrict__ rxm, const int* __restrict__ rxn)
{
    const int tid = threadIdx.x;
    const int bid = blockIdx.x;
    const int lane = tid & 31;
    const int wid  = tid >> 5;
    const int node = bid*NTHR + tid;
    const bool valid = node < NNODES;

    int i = 0, j = 0, k = 0, base4 = 0;
    if (valid) {
        k = node % 33;
        int ij = node / 33;
        j = ij % 65;
        i = ij / 65;
        base4 = node * 4;
    }

    // receiver-slot ownership (32 distinct nodes); zero our slot's x entries
    int slot = -1;
    if (valid) {
        for (int r2 = 0; r2 < 16; r2++) {
            if (node == rxm[r2]) slot = r2;
            if (node == rxn[r2]) slot = 16 + r2;
        }
        if (slot >= 0) {
            float4 z = make_float4(0.f, 0.f, 0.f, 0.f);
            float4* xs = (float4*)&g_xsel[slot*16];
            xs[0] = z; xs[1] = z; xs[2] = z; xs[3] = z;
        }
    }

    // r = b in registers
    float rr[16];
    #pragma unroll
    for (int s = 0; s < 16; s++) rr[s] = 0.f;
    if (valid) {
        #pragma unroll
        for (int s = 0; s < 16; s++) {
            if (node == sa[s]) rr[s] += 1.f;
            if (node == sb[s]) rr[s] -= 1.f;
        }
    }

    __shared__ float  s_red[32*16];
    __shared__ float  s_cross[16];
    __shared__ double s_dred[64];
    __shared__ float  s_alpha[16], s_beta[16], s_gamma[16];
    __shared__ int    s_frozen[16];
    if (tid < 16) { s_beta[tid] = 0.f; s_gamma[tid] = 2.f; s_frozen[tid] = 0; }
    __syncthreads();

    unsigned gen = g_rel;   // stable from previous launch

    float pp[16], qq[16];
    #pragma unroll
    for (int s = 0; s < 16; s++) pp[s] = 0.f;

    #pragma unroll 1
    for (int it = 0; it < CG_ITERS; ++it) {
        // ---- phase 1: p = r + beta*p; publish p ----
        if (valid) {
            #pragma unroll
            for (int s = 0; s < 16; s++) pp[s] = fmaf(s_beta[s], pp[s], rr[s]);
            #pragma unroll
            for (int u = 0; u < 4; u++)
                g_p[base4+u] = make_float4(pp[4*u], pp[4*u+1], pp[4*u+2], pp[4*u+3]);
        }
        gsync(++gen);

        // ---- phase 2: q = A p ; block-partial p.q ----
        if (valid) {
            #pragma unroll
            for (int s = 0; s < 16; s++) qq[s] = EPSD * pp[s];
            if (i < 64) NB(base4 + 4*2145, g_cx[(i*65 + j)*33 + k]);
            if (i > 0)  NB(base4 - 4*2145, g_cx[((i-1)*65 + j)*33 + k]);
            if (j < 64) NB(base4 + 4*33,   g_cy[(i*64 + j)*33 + k]);
            if (j > 0)  NB(base4 - 4*33,   g_cy[(i*64 + (j-1))*33 + k]);
            if (k < 32) NB(base4 + 4,      g_cz[(i*65 + j)*32 + k]);
            if (k > 0)  NB(base4 - 4,      g_cz[(i*65 + j)*32 + (k-1)]);
        } else {
            #pragma unroll
            for (int s = 0; s < 16; s++) qq[s] = 0.f;
        }
        BLOCKRED(valid ? pp[s]*qq[s] : 0.f, g_pqpart + bid*16);
        gsync(++gen);

        // ---- phase 3: alpha; r -= alpha q; x_rx += alpha p; partial r.r ----
        if (tid < 64) {
            int s = tid & 15, prt = tid >> 4;
            double acc = 0.0;
            for (int b = prt; b < NBLK; b += 4) acc += (double)g_pqpart[b*16 + s];
            s_dred[tid] = acc;
        }
        __syncthreads();
        if (tid < 16) {
            double pq = s_dred[tid] + s_dred[16+tid] + s_dred[32+tid] + s_dred[48+tid];
            s_alpha[tid] = s_frozen[tid] ? 0.f : s_gamma[tid] / (float)pq;
        }
        __syncthreads();
        if (valid) {
            #pragma unroll
            for (int s = 0; s < 16; s++) rr[s] = fmaf(-s_alpha[s], qq[s], rr[s]);
            if (slot >= 0) {
                #pragma unroll
                for (int s = 0; s < 16; s++)
                    g_xsel[slot*16 + s] += s_alpha[s] * pp[s];
            }
        }
        BLOCKRED(valid ? rr[s]*rr[s] : 0.f, g_g2part + bid*16);
        gsync(++gen);

        // ---- tail: gamma_new, beta, frozen ----
        if (tid < 64) {
            int s = tid & 15, prt = tid >> 4;
            double acc = 0.0;
            for (int b = prt; b < NBLK; b += 4) acc += (double)g_g2part[b*16 + s];
            s_dred[tid] = acc;
        }
        __syncthreads();
        if (tid < 16) {
            double gn = s_dred[tid] + s_dred[16+tid] + s_dred[32+tid] + s_dred[48+tid];
            float gnf = (float)gn;
            float b = s_frozen[tid] ? 0.f : gnf / s_gamma[tid];
            s_gamma[tid] = gnf;
            if (gn <= ATOL2) s_frozen[tid] = 1;
            s_beta[tid] = b;
        }
        __syncthreads();
    }
}

// ---------------- loss ----------------
__global__ void k_loss(const float* __restrict__ infm, const float* __restrict__ start,
                       const float* __restrict__ ref, float* __restrict__ out) {
    __shared__ double sd[256];
    __shared__ double sm[256];
    int t = threadIdx.x;
    int s = t >> 4;                   // source index
    int r = t & 15;                   // receiver index
    float d = g_xsel[r*16 + s] - g_xsel[(16+r)*16 + s];
    float diff = d - ref[t];
    sd[t] = (double)diff * (double)diff;
    double lm = 0.0;
    for (int idx = t; idx < NACT; idx += 256) {
        float dd = infm[idx] - start[idx];
        lm += (double)dd * (double)dd;
    }
    sm[t] = lm;
    __syncthreads();
    for (int off = 128; off >= 1; off >>= 1) {
        if (t < off) { sd[t] += sd[t+off]; sm[t] += sm[t+off]; }
        __syncthreads();
    }
    if (t == 0) {
        float loss_data  = (float)(sd[0] / 256.0);
        float loss_model = (float)(sm[0] / (double)NACT);
        out[0] = loss_data;           // alpha = 0.0 -> total == loss_data
        out[1] = loss_data;
        out[2] = loss_model;
    }
}

// ---------------- launch ----------------
extern "C" void kernel_launch(void* const* d_in, const int* in_sizes, int n_in,
                              void* d_out, int out_size) {
    const float* infm  = (const float*)d_in[0];
    const float* start = (const float*)d_in[1];
    const float* dref  = (const float*)d_in[2];
    const int*   act   = (const int*)  d_in[3];
    const int*   sa    = (const int*)  d_in[4];
    const int*   sb    = (const int*)  d_in[5];
    const int*   rxm   = (const int*)  d_in[6];
    const int*   rxn   = (const int*)  d_in[7];
    float* out = (float*)d_out;

    k_init_sigma<<<(NCELLS+255)/256, 256>>>();
    k_scatter<<<(NACT+255)/256, 256>>>(act, infm);
    k_coeffs<<<(NCX+NCY+NCZ+255)/256, 256>>>();
    k_persist<<<NBLK, NTHR>>>(sa, sb, rxm, rxn);
    k_loss<<<1, 256>>>(infm, start, dref, out);
}

// round 3
// speedup vs baseline: 1.5632x; 1.0236x over previous
#include <cuda_runtime.h>

// ---------------- problem constants ----------------
#define NNODES 139425          // 65*65*33
#define NCELLS 131072          // 64*64*32
#define NACT   81920
#define EPSD   1.0e-7f
#define ATOL2  2.0e-12         // (1e-6)^2 * ||b||^2, ||b||^2 = 2
#define NCX 137280             // 64*65*33
#define NCY 137280             // 65*64*33
#define NCZ 135200             // 65*65*32
#define CG_ITERS 100
#define NBLK 148
#define NTHR 1024

// ---------------- device scratch ----------------
__device__ float4 g_p[NNODES*4];
__device__ float  g_sigma[NCELLS];
__device__ float  g_cx[NCX];
__device__ float  g_cy[NCY];
__device__ float  g_cz[NCZ];
__device__ float  g_pqpart[NBLK*16];
__device__ float  g_g2part[NBLK*16];
__device__ float  g_xsel[32*16];
__device__ volatile unsigned g_arr[NBLK];
__device__ volatile unsigned g_rel;

// ---------------- setup kernels ----------------
__global__ void k_init_sigma() {
    int t = blockIdx.x*blockDim.x + threadIdx.x;
    if (t < NCELLS) g_sigma[t] = 1.0e-8f;            // 1/AIR_RES
}

__global__ void k_scatter(const int* __restrict__ act, const float* __restrict__ model) {
    int t = blockIdx.x*blockDim.x + threadIdx.x;
    if (t < NACT) g_sigma[act[t]] = 1.0f / model[t];
}

__global__ void k_coeffs() {
    int t = blockIdx.x*blockDim.x + threadIdx.x;
    if (t < NCX) {
        int k = t % 33; int r = t / 33; int j = r % 65; int i = r / 65;
        float s = 0.f;
        for (int jj = j-1; jj <= j; ++jj)
            for (int kk = k-1; kk <= k; ++kk)
                if (jj >= 0 && jj < 64 && kk >= 0 && kk < 32)
                    s += g_sigma[(i*64 + jj)*32 + kk];
        g_cx[t] = 6.25f * s;                          // 0.25 * 25.0
    } else if (t < NCX + NCY) {
        int e = t - NCX;
        int k = e % 33; int r = e / 33; int j = r % 64; int i = r / 64;
        float s = 0.f;
        for (int ii = i-1; ii <= i; ++ii)
            for (int kk = k-1; kk <= k; ++kk)
                if (ii >= 0 && ii < 64 && kk >= 0 && kk < 32)
                    s += g_sigma[(ii*64 + j)*32 + kk];
        g_cy[e] = 6.25f * s;
    } else if (t < NCX + NCY + NCZ) {
        int e = t - NCX - NCY;
        int k = e % 32; int r = e / 32; int j = r % 65; int i = r / 65;
        float s = 0.f;
        for (int ii = i-1; ii <= i; ++ii)
            for (int jj = j-1; jj <= j; ++jj)
                if (ii >= 0 && ii < 64 && jj >= 0 && jj < 64)
                    s += g_sigma[(ii*64 + jj)*32 + k];
        g_cz[e] = 6.25f * s;
    }
}

// ---------------- software grid barrier ----------------
__device__ __forceinline__ void gsync(unsigned target) {
    __syncthreads();
    if (threadIdx.x == 0) {
        __threadfence();                 // flush + order this block's writes
        g_arr[blockIdx.x] = target;
    }
    if (blockIdx.x == 0) {
        if (threadIdx.x < 32) {
            for (int b = (int)threadIdx.x; b < NBLK; b += 32) {
                while (g_arr[b] < target) { }
            }
            __syncwarp();
            if (threadIdx.x == 0) { __threadfence(); g_rel = target; }
        }
    } else {
        if (threadIdx.x == 0) {
            while (g_rel < target) { }
            __threadfence();             // invalidate L1 -> see fresh data
        }
    }
    __syncthreads();
}

// block reduction: EXPR(s) summed over the block -> gout[0..15] (float)
#define BLOCKRED(EXPR, gout)                                                   \
    {                                                                          \
        _Pragma("unroll")                                                      \
        for (int s = 0; s < 16; s++) {                                         \
            float v = (EXPR);                                                  \
            v += __shfl_down_sync(0xffffffffu, v, 16);                         \
            v += __shfl_down_sync(0xffffffffu, v, 8);                          \
            v += __shfl_down_sync(0xffffffffu, v, 4);                          \
            v += __shfl_down_sync(0xffffffffu, v, 2);                          \
            v += __shfl_down_sync(0xffffffffu, v, 1);                          \
            if (lane == 0) s_red[wid*16 + s] = v;                              \
        }                                                                      \
        __syncthreads();                                                       \
        if (tid < 16) {                                                        \
            float acc = 0.f;                                                   \
            _Pragma("unroll")                                                  \
            for (int w = 0; w < 32; w++) acc += s_red[w*16 + tid];             \
            s_cross[tid] = acc;                                                \
        }                                                                      \
        __syncthreads();                                                       \
        if (tid == 0) {                                                        \
            float4* o = (float4*)(gout);                                       \
            const float4* c = (const float4*)s_cross;                          \
            o[0] = c[0]; o[1] = c[1]; o[2] = c[2]; o[3] = c[3];                \
        }                                                                      \
    }

// one stencil direction: q += c * (p - p_neighbor)
#define NB(nb4, cval)                                                          \
    {                                                                          \
        float c_ = (cval);                                                     \
        _Pragma("unroll")                                                      \
        for (int u = 0; u < 4; u++) {                                          \
            float4 pn = g_p[(nb4) + u];                                        \
            qq[4*u+0] += c_*(pp[4*u+0] - pn.x);                                \
            qq[4*u+1] += c_*(pp[4*u+1] - pn.y);                                \
            qq[4*u+2] += c_*(pp[4*u+2] - pn.z);                                \
            qq[4*u+3] += c_*(pp[4*u+3] - pn.w);                                \
        }                                                                      \
    }

// ---------------- persistent CG kernel ----------------
__global__ void __launch_bounds__(NTHR, 1)
k_persist(const int* __restrict__ sa, const int* __restrict__ sb,
          const int* __restrict__ rxm, const int* __restrict__ rxn)
{
    const int tid = threadIdx.x;
    const int bid = blockIdx.x;
    const int lane = tid & 31;
    const int wid  = tid >> 5;
    const int node = bid*NTHR + tid;
    const bool valid = node < NNODES;

    int i = 0, j = 0, k = 0, base4 = 0;
    if (valid) {
        k = node % 33;
        int ij = node / 33;
        j = ij % 65;
        i = ij / 65;
        base4 = node * 4;
    }

    // receiver-slot ownership (32 distinct nodes); zero our slot's x entries
    int slot = -1;
    if (valid) {
        for (int r2 = 0; r2 < 16; r2++) {
            if (node == rxm[r2]) slot = r2;
            if (node == rxn[r2]) slot = 16 + r2;
        }
        if (slot >= 0) {
            float4 z = make_float4(0.f, 0.f, 0.f, 0.f);
            float4* xs = (float4*)&g_xsel[slot*16];
            xs[0] = z; xs[1] = z; xs[2] = z; xs[3] = z;
        }
    }

    // r = b in registers (persistent state: rr[16] + qq[16] only)
    float rr[16];
    #pragma unroll
    for (int s = 0; s < 16; s++) rr[s] = 0.f;
    if (valid) {
        #pragma unroll
        for (int s = 0; s < 16; s++) {
            if (node == sa[s]) rr[s] += 1.f;
            if (node == sb[s]) rr[s] -= 1.f;
        }
    }

    __shared__ float  s_red[32*16];
    __shared__ float  s_cross[16];
    __shared__ double s_dred[64];
    __shared__ float  s_alpha[16], s_beta[16], s_gamma[16];
    __shared__ int    s_frozen[16];
    if (tid < 16) { s_beta[tid] = 0.f; s_gamma[tid] = 2.f; s_frozen[tid] = 0; }
    __syncthreads();

    unsigned gen = g_rel;   // stable from previous launch

    float qq[16];
    #pragma unroll
    for (int s = 0; s < 16; s++) qq[s] = 0.f;

    #pragma unroll 1
    for (int it = 0; it < CG_ITERS; ++it) {
        // ---- phase 1: p = r + beta*p_old (RMW in global, owner-only) ----
        if (valid) {
            #pragma unroll
            for (int u = 0; u < 4; u++) {
                float4 po = g_p[base4+u];
                float4 pv;
                pv.x = fmaf(s_beta[4*u+0], po.x, rr[4*u+0]);
                pv.y = fmaf(s_beta[4*u+1], po.y, rr[4*u+1]);
                pv.z = fmaf(s_beta[4*u+2], po.z, rr[4*u+2]);
                pv.w = fmaf(s_beta[4*u+3], po.w, rr[4*u+3]);
                g_p[base4+u] = pv;
            }
        }
        gsync(++gen);

        // ---- phase 2: q = A p ; block-partial p.q (p phase-local in regs) ----
        {
            float pp[16];
            if (valid) {
                #pragma unroll
                for (int u = 0; u < 4; u++) {
                    float4 pv = g_p[base4+u];
                    pp[4*u+0] = pv.x; pp[4*u+1] = pv.y;
                    pp[4*u+2] = pv.z; pp[4*u+3] = pv.w;
                }
                #pragma unroll
                for (int s = 0; s < 16; s++) qq[s] = EPSD * pp[s];
                if (i < 64) NB(base4 + 4*2145, g_cx[(i*65 + j)*33 + k]);
                if (i > 0)  NB(base4 - 4*2145, g_cx[((i-1)*65 + j)*33 + k]);
                if (j < 64) NB(base4 + 4*33,   g_cy[(i*64 + j)*33 + k]);
                if (j > 0)  NB(base4 - 4*33,   g_cy[(i*64 + (j-1))*33 + k]);
                if (k < 32) NB(base4 + 4,      g_cz[(i*65 + j)*32 + k]);
                if (k > 0)  NB(base4 - 4,      g_cz[(i*65 + j)*32 + (k-1)]);
            } else {
                #pragma unroll
                for (int s = 0; s < 16; s++) { pp[s] = 0.f; qq[s] = 0.f; }
            }
            BLOCKRED(pp[s]*qq[s], g_pqpart + bid*16);
        }
        gsync(++gen);

        // ---- phase 3: alpha; r -= alpha q; x_rx += alpha p; partial r.r ----
        if (tid < 64) {
            int s = tid & 15, prt = tid >> 4;
            double acc = 0.0;
            for (int b = prt; b < NBLK; b += 4) acc += (double)g_pqpart[b*16 + s];
            s_dred[tid] = acc;
        }
        __syncthreads();
        if (tid < 16) {
            double pq = s_dred[tid] + s_dred[16+tid] + s_dred[32+tid] + s_dred[48+tid];
            s_alpha[tid] = s_frozen[tid] ? 0.f : s_gamma[tid] / (float)pq;
        }
        __syncthreads();
        if (valid) {
            #pragma unroll
            for (int s = 0; s < 16; s++) rr[s] = fmaf(-s_alpha[s], qq[s], rr[s]);
            if (slot >= 0) {
                #pragma unroll
                for (int u = 0; u < 4; u++) {
                    float4 pv = g_p[base4+u];
                    g_xsel[slot*16 + 4*u+0] += s_alpha[4*u+0] * pv.x;
                    g_xsel[slot*16 + 4*u+1] += s_alpha[4*u+1] * pv.y;
                    g_xsel[slot*16 + 4*u+2] += s_alpha[4*u+2] * pv.z;
                    g_xsel[slot*16 + 4*u+3] += s_alpha[4*u+3] * pv.w;
                }
            }
        }
        BLOCKRED(valid ? rr[s]*rr[s] : 0.f, g_g2part + bid*16);
        gsync(++gen);

        // ---- tail: gamma_new, beta, frozen ----
        if (tid < 64) {
            int s = tid & 15, prt = tid >> 4;
            double acc = 0.0;
            for (int b = prt; b < NBLK; b += 4) acc += (double)g_g2part[b*16 + s];
            s_dred[tid] = acc;
        }
        __syncthreads();
        if (tid < 16) {
            double gn = s_dred[tid] + s_dred[16+tid] + s_dred[32+tid] + s_dred[48+tid];
            float gnf = (float)gn;
            float b = s_frozen[tid] ? 0.f : gnf / s_gamma[tid];
            s_gamma[tid] = gnf;
            if (gn <= ATOL2) s_frozen[tid] = 1;
            s_beta[tid] = b;
        }
        __syncthreads();
    }
}

// ---------------- loss ----------------
__global__ void k_loss(const float* __restrict__ infm, const float* __restrict__ start,
                       const float* __restrict__ ref, float* __restrict__ out) {
    __shared__ double sd[256];
    __shared__ double sm[256];
    int t = threadIdx.x;
    int s = t >> 4;                   // source index
    int r = t & 15;                   // receiver index
    float d = g_xsel[r*16 + s] - g_xsel[(16+r)*16 + s];
    float diff = d - ref[t];
    sd[t] = (double)diff * (double)diff;
    double lm = 0.0;
    for (int idx = t; idx < NACT; idx += 256) {
        float dd = infm[idx] - start[idx];
        lm += (double)dd * (double)dd;
    }
    sm[t] = lm;
    __syncthreads();
    for (int off = 128; off >= 1; off >>= 1) {
        if (t < off) { sd[t] += sd[t+off]; sm[t] += sm[t+off]; }
        __syncthreads();
    }
    if (t == 0) {
        float loss_data  = (float)(sd[0] / 256.0);
        float loss_model = (float)(sm[0] / (double)NACT);
        out[0] = loss_data;           // alpha = 0.0 -> total == loss_data
        out[1] = loss_data;
        out[2] = loss_model;
    }
}

// ---------------- launch ----------------
extern "C" void kernel_launch(void* const* d_in, const int* in_sizes, int n_in,
                              void* d_out, int out_size) {
    const float* infm  = (const float*)d_in[0];
    const float* start = (const float*)d_in[1];
    const float* dref  = (const float*)d_in[2];
    const int*   act   = (const int*)  d_in[3];
    const int*   sa    = (const int*)  d_in[4];
    const int*   sb    = (const int*)  d_in[5];
    const int*   rxm   = (const int*)  d_in[6];
    const int*   rxn   = (const int*)  d_in[7];
    float* out = (float*)d_out;

    k_init_sigma<<<(NCELLS+255)/256, 256>>>();
    k_scatter<<<(NACT+255)/256, 256>>>(act, infm);
    k_coeffs<<<(NCX+NCY+NCZ+255)/256, 256>>>();
    k_persist<<<NBLK, NTHR>>>(sa, sb, rxm, rxn);
    k_loss<<<1, 256>>>(infm, start, dref, out);
}